// round 3
// baseline (speedup 1.0000x reference)
#include <cuda_runtime.h>

#define S_TOT 4096
#define N_OBJ 32
#define H_D   64
#define PADF  68   // padded floats per 64-float row

typedef unsigned long long u64;

// ---- all weights live in the constant bank (off the LDS crossbar) ----
__constant__ float cL1W[H_D * 4];
__constant__ float cL1b[H_D];
__constant__ float cL2W[H_D * H_D];
__constant__ float cL2b[H_D];
__constant__ float cI1W[H_D * H_D];
__constant__ float cI2W[8 * H_D];
__constant__ float cS1W[16];
__constant__ float cS1b[4];
__constant__ float cS2W[N_OBJ * 4];
__constant__ float cS2b[N_OBJ * 2];

__device__ __forceinline__ u64 pack2(float lo, float hi) {
    u64 r; asm("mov.b64 %0, {%1, %2};" : "=l"(r) : "f"(lo), "f"(hi)); return r;
}
__device__ __forceinline__ void unpack2(u64 v, float& lo, float& hi) {
    asm("mov.b64 {%0, %1}, %2;" : "=f"(lo), "=f"(hi) : "l"(v));
}
// Blackwell packed f32x2 FMA: d = a*b + c (elementwise on 2 floats)
__device__ __forceinline__ u64 ffma2(u64 a, u64 b, u64 c) {
    u64 d; asm("fma.rn.f32x2 %0, %1, %2, %3;" : "=l"(d) : "l"(a), "l"(b), "l"(c)); return d;
}
// 1-MUFU tanh for inner nonlinearity (error ~1e-4 abs, damped by 0.01 I3 weights)
__device__ __forceinline__ float tanh_fast(float x) {
    float y; asm("tanh.approx.f32 %0, %1;" : "=f"(y) : "f"(x)); return y;
}
// exact-ish tanh for the 8 outer activations (~1e-7 rel)
__device__ __forceinline__ float tanh_exact(float x) {
    float e = __expf(2.f * x);
    return 1.f - __fdividef(2.f, e + 1.f);
}

__global__ __launch_bounds__(512, 2)
void magnet_main(const float* __restrict__ X,    // [S,32,4]
                 const float* __restrict__ I3,   // [992,2,4]
                 float* __restrict__ out)        // [S,32,2]
{
    __shared__ __align__(16) float bufA[N_OBJ * PADF];
    __shared__ __align__(16) float bufB[N_OBJ * PADF];
    __shared__ __align__(16) float sX[N_OBJ * 4];
    __shared__ float sRes[N_OBJ * 2];

    const int tid = threadIdx.x;
    const int s   = blockIdx.x;

    if (tid < 128) sX[tid] = X[s * 128 + tid];
    __syncthreads();

    const int io = tid & 31;        // object
    const int c0 = (tid >> 5) * 4;  // 4 output channels (warp-uniform)
    float* rowA = &bufA[io * PADF];
    float* rowB = &bufB[io * PADF];

    // ---- h1 = relu(x @ L1W^T + L1b) -> bufA ----
    {
        float4 xv = ((const float4*)sX)[io];
        float4 o;
        float* op = (float*)&o;
        #pragma unroll
        for (int q = 0; q < 4; q++) {
            int c = c0 + q;
            float4 w = ((const float4*)cL1W)[c];
            op[q] = fmaxf(fmaf(xv.x, w.x, fmaf(xv.y, w.y,
                     fmaf(xv.z, w.z, fmaf(xv.w, w.w, cL1b[c])))), 0.f);
        }
        *((float4*)(rowA + c0)) = o;
    }
    // ---- self term -> sRes (init) ----
    if (tid < N_OBJ) {
        float4 xv = ((const float4*)sX)[tid];
        float hs[4];
        #pragma unroll
        for (int f = 0; f < 4; f++) {
            float4 w = ((const float4*)cS1W)[f];
            hs[f] = fmaxf(xv.x*w.x + xv.y*w.y + xv.z*w.z + xv.w*w.w + cS1b[f], 0.f);
        }
        float4 s2 = ((const float4*)cS2W)[tid];
        sRes[tid * 2 + 0] = hs[0] * s2.x + hs[1] * s2.y + cS2b[tid * 2 + 0];
        sRes[tid * 2 + 1] = hs[2] * s2.z + hs[3] * s2.w + cS2b[tid * 2 + 1];
    }
    __syncthreads();

    // ---- h2 = relu(h1 @ L2W^T + L2b) -> bufB  (FFMA2 over k-pairs) ----
    {
        u64 a0 = pack2(cL2b[c0 + 0], 0.f);
        u64 a1 = pack2(cL2b[c0 + 1], 0.f);
        u64 a2 = pack2(cL2b[c0 + 2], 0.f);
        u64 a3 = pack2(cL2b[c0 + 3], 0.f);
        const float4* hv = (const float4*)rowA;
        #pragma unroll
        for (int k4 = 0; k4 < 16; k4++) {
            float4 h = hv[k4];
            u64 h01 = pack2(h.x, h.y), h23 = pack2(h.z, h.w);
            ulonglong2 w0 = ((const ulonglong2*)&cL2W[(c0 + 0) * 64])[k4];
            a0 = ffma2(h01, w0.x, a0); a0 = ffma2(h23, w0.y, a0);
            ulonglong2 w1 = ((const ulonglong2*)&cL2W[(c0 + 1) * 64])[k4];
            a1 = ffma2(h01, w1.x, a1); a1 = ffma2(h23, w1.y, a1);
            ulonglong2 w2 = ((const ulonglong2*)&cL2W[(c0 + 2) * 64])[k4];
            a2 = ffma2(h01, w2.x, a2); a2 = ffma2(h23, w2.y, a2);
            ulonglong2 w3 = ((const ulonglong2*)&cL2W[(c0 + 3) * 64])[k4];
            a3 = ffma2(h01, w3.x, a3); a3 = ffma2(h23, w3.y, a3);
        }
        float lo, hi; float4 o;
        unpack2(a0, lo, hi); o.x = fmaxf(lo + hi, 0.f);
        unpack2(a1, lo, hi); o.y = fmaxf(lo + hi, 0.f);
        unpack2(a2, lo, hi); o.z = fmaxf(lo + hi, 0.f);
        unpack2(a3, lo, hi); o.w = fmaxf(lo + hi, 0.f);
        *((float4*)(rowB + c0)) = o;
    }
    __syncthreads();

    // ---- a = h2 @ I1W^T -> bufA  (diff @ I1W^T == a_i - a_j) ----
    {
        u64 a0 = 0, a1 = 0, a2 = 0, a3 = 0;
        const float4* hv = (const float4*)rowB;
        #pragma unroll
        for (int k4 = 0; k4 < 16; k4++) {
            float4 h = hv[k4];
            u64 h01 = pack2(h.x, h.y), h23 = pack2(h.z, h.w);
            ulonglong2 w0 = ((const ulonglong2*)&cI1W[(c0 + 0) * 64])[k4];
            a0 = ffma2(h01, w0.x, a0); a0 = ffma2(h23, w0.y, a0);
            ulonglong2 w1 = ((const ulonglong2*)&cI1W[(c0 + 1) * 64])[k4];
            a1 = ffma2(h01, w1.x, a1); a1 = ffma2(h23, w1.y, a1);
            ulonglong2 w2 = ((const ulonglong2*)&cI1W[(c0 + 2) * 64])[k4];
            a2 = ffma2(h01, w2.x, a2); a2 = ffma2(h23, w2.y, a2);
            ulonglong2 w3 = ((const ulonglong2*)&cI1W[(c0 + 3) * 64])[k4];
            a3 = ffma2(h01, w3.x, a3); a3 = ffma2(h23, w3.y, a3);
        }
        float lo, hi; float4 o;
        unpack2(a0, lo, hi); o.x = lo + hi;
        unpack2(a1, lo, hi); o.y = lo + hi;
        unpack2(a2, lo, hi); o.z = lo + hi;
        unpack2(a3, lo, hi); o.w = lo + hi;
        *((float4*)(rowA + c0)) = o;
    }
    __syncthreads();

    // ---- pair stage: thread = one i<j pair (antisymmetric halving) ----
    if (tid < 496) {
        int i = 0, rem = tid;
        while (rem >= 31 - i) { rem -= 31 - i; ++i; }
        int j = i + 1 + rem;

        const float4* ai = (const float4*)&bufA[i * PADF];
        const float4* aj = (const float4*)&bufA[j * PADF];

        u64 p[8] = {0, 0, 0, 0, 0, 0, 0, 0};  // f32x2 accum over h-pairs, per feature f
        #pragma unroll
        for (int k4 = 0; k4 < 16; k4++) {
            float4 av = ai[k4], bv = aj[k4];
            float t0 = tanh_fast(av.x - bv.x);
            float t1 = tanh_fast(av.y - bv.y);
            float t2 = tanh_fast(av.z - bv.z);
            float t3 = tanh_fast(av.w - bv.w);
            u64 t01 = pack2(t0, t1), t23 = pack2(t2, t3);
            #pragma unroll
            for (int f = 0; f < 8; f++) {
                ulonglong2 w = ((const ulonglong2*)&cI2W[f * 64])[k4];
                p[f] = ffma2(t01, w.x, p[f]);
                p[f] = ffma2(t23, w.y, p[f]);
            }
        }
        float t[8];
        #pragma unroll
        for (int f = 0; f < 8; f++) {
            float lo, hi; unpack2(p[f], lo, hi);
            t[f] = tanh_exact(lo + hi);
        }

        int idx_ij = i * 31 + (j - 1);
        int idx_ji = j * 31 + i;
        float4 gi0 = __ldg((const float4*)(I3 + idx_ij * 8));
        float4 gi1 = __ldg((const float4*)(I3 + idx_ij * 8) + 1);
        float4 gj0 = __ldg((const float4*)(I3 + idx_ji * 8));
        float4 gj1 = __ldg((const float4*)(I3 + idx_ji * 8) + 1);

        float ci0 = t[0]*gi0.x + t[1]*gi0.y + t[2]*gi0.z + t[3]*gi0.w;
        float ci1 = t[4]*gi1.x + t[5]*gi1.y + t[6]*gi1.z + t[7]*gi1.w;
        float cj0 = -(t[0]*gj0.x + t[1]*gj0.y + t[2]*gj0.z + t[3]*gj0.w);
        float cj1 = -(t[4]*gj1.x + t[5]*gj1.y + t[6]*gj1.z + t[7]*gj1.w);

        atomicAdd(&sRes[i * 2 + 0], ci0);
        atomicAdd(&sRes[i * 2 + 1], ci1);
        atomicAdd(&sRes[j * 2 + 0], cj0);
        atomicAdd(&sRes[j * 2 + 1], cj1);
    }
    __syncthreads();

    if (tid < 32)
        ((float2*)out)[s * 32 + tid] = ((float2*)sRes)[tid];
}

extern "C" void kernel_launch(void* const* d_in, const int* in_sizes, int n_in,
                              void* d_out, int out_size) {
    const float* inputs = (const float*)d_in[0];
    cudaMemcpyToSymbolAsync(cL1W, d_in[1],  H_D * 4 * 4,      0, cudaMemcpyDeviceToDevice, 0);
    cudaMemcpyToSymbolAsync(cL1b, d_in[2],  H_D * 4,          0, cudaMemcpyDeviceToDevice, 0);
    cudaMemcpyToSymbolAsync(cL2W, d_in[3],  H_D * H_D * 4,    0, cudaMemcpyDeviceToDevice, 0);
    cudaMemcpyToSymbolAsync(cL2b, d_in[4],  H_D * 4,          0, cudaMemcpyDeviceToDevice, 0);
    cudaMemcpyToSymbolAsync(cI1W, d_in[5],  H_D * H_D * 4,    0, cudaMemcpyDeviceToDevice, 0);
    cudaMemcpyToSymbolAsync(cI2W, d_in[6],  8 * H_D * 4,      0, cudaMemcpyDeviceToDevice, 0);
    cudaMemcpyToSymbolAsync(cS1W, d_in[8],  16 * 4,           0, cudaMemcpyDeviceToDevice, 0);
    cudaMemcpyToSymbolAsync(cS1b, d_in[9],  4 * 4,            0, cudaMemcpyDeviceToDevice, 0);
    cudaMemcpyToSymbolAsync(cS2W, d_in[10], N_OBJ * 4 * 4,    0, cudaMemcpyDeviceToDevice, 0);
    cudaMemcpyToSymbolAsync(cS2b, d_in[11], N_OBJ * 2 * 4,    0, cudaMemcpyDeviceToDevice, 0);

    const float* I3 = (const float*)d_in[7];
    float* out = (float*)d_out;
    magnet_main<<<S_TOT, 512>>>(inputs, I3, out);
}

// round 4
// speedup vs baseline: 7.1251x; 7.1251x over previous
#include <cuda_runtime.h>

#define S_TOT 4096
#define N_OBJ 32
#define H_D   64
#define PADT  35   // transposed-row stride: (35k+l)%32 = (3k+l)%32, conflict-free per lane

typedef unsigned long long u64;

__device__ __forceinline__ u64 pack2(float lo, float hi) {
    u64 r; asm("mov.b64 %0, {%1, %2};" : "=l"(r) : "f"(lo), "f"(hi)); return r;
}
__device__ __forceinline__ void unpack2(u64 v, float& lo, float& hi) {
    asm("mov.b64 {%0, %1}, %2;" : "=f"(lo), "=f"(hi) : "l"(v));
}
__device__ __forceinline__ u64 ffma2(u64 a, u64 b, u64 c) {
    u64 d; asm("fma.rn.f32x2 %0, %1, %2, %3;" : "=l"(d) : "l"(a), "l"(b), "l"(c)); return d;
}
// 1-MUFU tanh for the 64 inner nonlinearities (validated rel_err ~2e-6 in R3)
__device__ __forceinline__ float tanh_fast(float x) {
    float y; asm("tanh.approx.f32 %0, %1;" : "=f"(y) : "f"(x)); return y;
}
// exact-ish tanh for the 8 outer activations
__device__ __forceinline__ float tanh_exact(float x) {
    float e = __expf(2.f * x);
    return 1.f - __fdividef(2.f, e + 1.f);
}

__global__ __launch_bounds__(1024, 1)
void magnet_main(const float* __restrict__ X,     // [S,32,4]
                 const float* __restrict__ L1W,   // [64,4]
                 const float* __restrict__ L1b,   // [64]
                 const float* __restrict__ L2W,   // [64,64]
                 const float* __restrict__ L2b,   // [64]
                 const float* __restrict__ I1W,   // [64,64]
                 const float* __restrict__ I2W,   // [8,64]
                 const float* __restrict__ I3,    // [992,2,4]
                 const float* __restrict__ S1W,   // [4,4]
                 const float* __restrict__ S1b,   // [4]
                 const float* __restrict__ S2W,   // [32,2,2]
                 const float* __restrict__ S2b,   // [32,2]
                 float* __restrict__ out)         // [S,32,2]
{
    __shared__ float bufT1[2 * H_D * PADT];            // transposed activations [s][k][lane]
    __shared__ float bufT2[2 * H_D * PADT];
    __shared__ __align__(16) float sW[H_D * H_D];      // reused: L2W then I1W (row-major [c][k])
    __shared__ __align__(16) float sI2[H_D * 8];       // [h][f]
    __shared__ __align__(16) float sL1W[H_D * 4];
    __shared__ __align__(16) float sX[2 * N_OBJ * 4];
    __shared__ float sL1b[H_D];
    __shared__ float sL2b[H_D];
    __shared__ float sRes[2 * N_OBJ * 2];

    const int tid = threadIdx.x;
    const int s   = tid >> 9;       // sample within block (0/1)
    const int r   = tid & 511;
    const int wS  = r >> 5;         // warp within sample (0..15)
    const int lane = r & 31;        // = object in encoder stages
    const int c0  = wS * 4;         // 4 channels owned by this warp (warp-uniform)

    // ---- staging ----
    ((float4*)sW)[tid] = __ldg(((const float4*)L2W) + tid);   // 1024 x float4 = 4096 floats
    if (tid < 512) {                                          // sI2[h][f] = I2W[f][h]
        int h = tid >> 3, f = tid & 7;
        sI2[tid] = __ldg(I2W + f * 64 + h);
    } else if (tid < 576) sL1b[tid - 512] = __ldg(L1b + tid - 512);
    else if (tid < 640)   sL2b[tid - 576] = __ldg(L2b + tid - 576);
    else if (tid < 704)   ((float4*)sX)[tid - 640]  = __ldg(((const float4*)X) + blockIdx.x * 64 + (tid - 640));
    else if (tid < 768)   ((float4*)sL1W)[tid - 704] = __ldg(((const float4*)L1W) + (tid - 704));
    __syncthreads();

    // ---- stage 1: h1 = relu(x @ L1W^T + L1b), write transposed ----
    {
        float4 xv = ((const float4*)sX)[s * N_OBJ + lane];
        #pragma unroll
        for (int q = 0; q < 4; q++) {
            int c = c0 + q;
            float4 w = ((const float4*)sL1W)[c];               // broadcast
            float v = fmaf(xv.x, w.x, fmaf(xv.y, w.y,
                      fmaf(xv.z, w.z, fmaf(xv.w, w.w, sL1b[c]))));
            bufT1[(s * H_D + c) * PADT + lane] = fmaxf(v, 0.f);
        }
    }
    // ---- self term -> sRes (init) ----
    if (tid < 64) {
        int ii = tid & 31;
        float4 xv = ((const float4*)sX)[tid];
        float hs[4];
        #pragma unroll
        for (int f = 0; f < 4; f++) {
            float4 w = __ldg(((const float4*)S1W) + f);
            hs[f] = fmaxf(xv.x*w.x + xv.y*w.y + xv.z*w.z + xv.w*w.w + __ldg(S1b + f), 0.f);
        }
        float4 s2 = __ldg(((const float4*)S2W) + ii);
        sRes[tid * 2 + 0] = hs[0] * s2.x + hs[1] * s2.y + __ldg(S2b + ii * 2 + 0);
        sRes[tid * 2 + 1] = hs[2] * s2.z + hs[3] * s2.w + __ldg(S2b + ii * 2 + 1);
    }
    __syncthreads();

    // ---- stage 2: h2 = relu(h1 @ L2W^T + L2b) -> bufT2 ----
    {
        u64 acc[4];
        #pragma unroll
        for (int q = 0; q < 4; q++) acc[q] = pack2(sL2b[c0 + q], 0.f);
        #pragma unroll
        for (int k4 = 0; k4 < 16; k4++) {
            int kb = k4 * 4;
            float h0 = bufT1[(s * H_D + kb + 0) * PADT + lane];
            float h1 = bufT1[(s * H_D + kb + 1) * PADT + lane];
            float h2 = bufT1[(s * H_D + kb + 2) * PADT + lane];
            float h3 = bufT1[(s * H_D + kb + 3) * PADT + lane];
            u64 h01 = pack2(h0, h1), h23 = pack2(h2, h3);
            #pragma unroll
            for (int q = 0; q < 4; q++) {
                ulonglong2 w = *(const ulonglong2*)&sW[(c0 + q) * 64 + kb];  // broadcast
                acc[q] = ffma2(h01, w.x, acc[q]);
                acc[q] = ffma2(h23, w.y, acc[q]);
            }
        }
        #pragma unroll
        for (int q = 0; q < 4; q++) {
            float lo, hi; unpack2(acc[q], lo, hi);
            bufT2[(s * H_D + c0 + q) * PADT + lane] = fmaxf(lo + hi, 0.f);
        }
    }
    __syncthreads();

    // ---- restage weights: sW <- I1W ----
    ((float4*)sW)[tid] = __ldg(((const float4*)I1W) + tid);
    __syncthreads();

    // ---- stage 3: a = h2 @ I1W^T -> bufT1 (diff @ I1W^T == a_i - a_j) ----
    {
        u64 acc[4] = {0, 0, 0, 0};
        #pragma unroll
        for (int k4 = 0; k4 < 16; k4++) {
            int kb = k4 * 4;
            float h0 = bufT2[(s * H_D + kb + 0) * PADT + lane];
            float h1 = bufT2[(s * H_D + kb + 1) * PADT + lane];
            float h2 = bufT2[(s * H_D + kb + 2) * PADT + lane];
            float h3 = bufT2[(s * H_D + kb + 3) * PADT + lane];
            u64 h01 = pack2(h0, h1), h23 = pack2(h2, h3);
            #pragma unroll
            for (int q = 0; q < 4; q++) {
                ulonglong2 w = *(const ulonglong2*)&sW[(c0 + q) * 64 + kb];
                acc[q] = ffma2(h01, w.x, acc[q]);
                acc[q] = ffma2(h23, w.y, acc[q]);
            }
        }
        #pragma unroll
        for (int q = 0; q < 4; q++) {
            float lo, hi; unpack2(acc[q], lo, hi);
            bufT1[(s * H_D + c0 + q) * PADT + lane] = lo + hi;
        }
    }
    __syncthreads();

    // ---- pair stage: thread = one i<j pair (antisymmetric halving) ----
    if (r < 496) {
        int i = 0, rem = r;
        while (rem >= 31 - i) { rem -= 31 - i; ++i; }
        int j = i + 1 + rem;

        const float* aT = &bufT1[s * H_D * PADT];
        u64 p01 = 0, p23 = 0, p45 = 0, p67 = 0;   // feature pairs packed f32x2
        #pragma unroll 16
        for (int h = 0; h < H_D; h++) {
            float d = aT[h * PADT + i] - aT[h * PADT + j];   // conflict-free scalar LDS
            float t = tanh_fast(d);
            u64 tt = pack2(t, t);
            const ulonglong2* wp = (const ulonglong2*)&sI2[h * 8];
            ulonglong2 wa = wp[0], wb = wp[1];                // broadcast
            p01 = ffma2(tt, wa.x, p01);
            p23 = ffma2(tt, wa.y, p23);
            p45 = ffma2(tt, wb.x, p45);
            p67 = ffma2(tt, wb.y, p67);
        }
        float t[8];
        unpack2(p01, t[0], t[1]); unpack2(p23, t[2], t[3]);
        unpack2(p45, t[4], t[5]); unpack2(p67, t[6], t[7]);
        #pragma unroll
        for (int f = 0; f < 8; f++) t[f] = tanh_exact(t[f]);

        int idx_ij = i * 31 + (j - 1);
        int idx_ji = j * 31 + i;
        float4 gi0 = __ldg((const float4*)(I3 + idx_ij * 8));
        float4 gi1 = __ldg((const float4*)(I3 + idx_ij * 8) + 1);
        float4 gj0 = __ldg((const float4*)(I3 + idx_ji * 8));
        float4 gj1 = __ldg((const float4*)(I3 + idx_ji * 8) + 1);

        float ci0 = t[0]*gi0.x + t[1]*gi0.y + t[2]*gi0.z + t[3]*gi0.w;
        float ci1 = t[4]*gi1.x + t[5]*gi1.y + t[6]*gi1.z + t[7]*gi1.w;
        float cj0 = -(t[0]*gj0.x + t[1]*gj0.y + t[2]*gj0.z + t[3]*gj0.w);
        float cj1 = -(t[4]*gj1.x + t[5]*gj1.y + t[6]*gj1.z + t[7]*gj1.w);

        atomicAdd(&sRes[(s * N_OBJ + i) * 2 + 0], ci0);
        atomicAdd(&sRes[(s * N_OBJ + i) * 2 + 1], ci1);
        atomicAdd(&sRes[(s * N_OBJ + j) * 2 + 0], cj0);
        atomicAdd(&sRes[(s * N_OBJ + j) * 2 + 1], cj1);
    }
    __syncthreads();

    // ---- write out: 2 samples x 32 obj x 2 ----
    if (tid < 64)
        ((float2*)out)[blockIdx.x * 64 + tid] = ((float2*)sRes)[tid];
}

extern "C" void kernel_launch(void* const* d_in, const int* in_sizes, int n_in,
                              void* d_out, int out_size) {
    const float* inputs = (const float*)d_in[0];
    const float* L1W    = (const float*)d_in[1];
    const float* L1b    = (const float*)d_in[2];
    const float* L2W    = (const float*)d_in[3];
    const float* L2b    = (const float*)d_in[4];
    const float* I1W    = (const float*)d_in[5];
    const float* I2W    = (const float*)d_in[6];
    const float* I3     = (const float*)d_in[7];
    const float* S1W    = (const float*)d_in[8];
    const float* S1b    = (const float*)d_in[9];
    const float* S2W    = (const float*)d_in[10];
    const float* S2b    = (const float*)d_in[11];
    float* out = (float*)d_out;

    magnet_main<<<S_TOT / 2, 1024>>>(inputs, L1W, L1b, L2W, L2b,
                                     I1W, I2W, I3, S1W, S1b, S2W, S2b, out);
}

// round 5
// speedup vs baseline: 8.3015x; 1.1651x over previous
#include <cuda_runtime.h>

#define S_TOT 4096
#define N_OBJ 32
#define H_D   64
#define PADT  35   // transposed stride (scalar lane reads conflict-free)
#define PADF  68   // row-major stride (float4 reads/writes conflict-free)
#define NPAIR 496

typedef unsigned long long u64;

__device__ __forceinline__ u64 pack2(float lo, float hi) {
    u64 r; asm("mov.b64 %0, {%1, %2};" : "=l"(r) : "f"(lo), "f"(hi)); return r;
}
__device__ __forceinline__ void unpack2(u64 v, float& lo, float& hi) {
    asm("mov.b64 {%0, %1}, %2;" : "=f"(lo), "=f"(hi) : "l"(v));
}
__device__ __forceinline__ u64 ffma2(u64 a, u64 b, u64 c) {
    u64 d; asm("fma.rn.f32x2 %0, %1, %2, %3;" : "=l"(d) : "l"(a), "l"(b), "l"(c)); return d;
}
__device__ __forceinline__ float tanh_fast(float x) {   // 1 MUFU (validated 2.3e-6 end-to-end)
    float y; asm("tanh.approx.f32 %0, %1;" : "=f"(y) : "f"(x)); return y;
}
__device__ __forceinline__ float tanh_exact(float x) {
    float e = __expf(2.f * x);
    return 1.f - __fdividef(2.f, e + 1.f);
}

__global__ __launch_bounds__(512, 2)
void magnet_main(const float* __restrict__ X,     // [S,32,4]
                 const float* __restrict__ L1W,   // [64,4]
                 const float* __restrict__ L1b,   // [64]
                 const float* __restrict__ L2W,   // [64,64]
                 const float* __restrict__ L2b,   // [64]
                 const float* __restrict__ I1W,   // [64,64]
                 const float* __restrict__ I2W,   // [8,64]
                 const float* __restrict__ I3,    // [992,2,4]
                 const float* __restrict__ S1W,   // [4,4]
                 const float* __restrict__ S1b,   // [4]
                 const float* __restrict__ S2W,   // [32,2,2]
                 const float* __restrict__ S2b,   // [32,2]
                 float* __restrict__ out)         // [S,32,2]
{
    __shared__ float bufT1[H_D * PADT];                // h1 transposed [k][lane]; reused as row-major a [i][PADF]
    __shared__ float bufT2[H_D * PADT];                // h2 transposed
    __shared__ __align__(16) float sWL2[H_D * H_D];    // L2W row-major [c][k]
    __shared__ __align__(16) float sWI1[H_D * H_D];    // I1W row-major [c][k]
    __shared__ __align__(16) float sI2[H_D * 8];       // [h][f]
    __shared__ __align__(16) float sPair[NPAIR * 4];   // per-pair (ci0,ci1,cj0,cj1)
    __shared__ __align__(16) float sX[N_OBJ * 4];
    __shared__ __align__(16) float sL1W[H_D * 4];
    __shared__ float sL1b[H_D];
    __shared__ float sL2b[H_D];
    __shared__ float sRes[N_OBJ * 2];

    const int tid  = threadIdx.x;
    const int s    = blockIdx.x;
    const int wS   = tid >> 5;       // warp 0..15
    const int lane = tid & 31;       // = object in encoder stages
    const int c0   = wS * 4;         // channels owned by this warp (warp-uniform)

    // ---- staging: both weight matrices, I2 transposed, misc ----
    {
        const float4* W2 = (const float4*)L2W;
        const float4* W1 = (const float4*)I1W;
        ((float4*)sWL2)[tid]       = __ldg(W2 + tid);
        ((float4*)sWL2)[tid + 512] = __ldg(W2 + tid + 512);
        ((float4*)sWI1)[tid]       = __ldg(W1 + tid);
        ((float4*)sWI1)[tid + 512] = __ldg(W1 + tid + 512);
        int h = tid >> 3, f = tid & 7;
        sI2[tid] = __ldg(I2W + f * 64 + h);              // sI2[h][f]
        if (tid < 32)       ((float4*)sX)[tid]        = __ldg(((const float4*)X) + s * 32 + tid);
        else if (tid < 96)  ((float4*)sL1W)[tid - 32] = __ldg(((const float4*)L1W) + (tid - 32));
        else if (tid < 160) sL1b[tid - 96]  = __ldg(L1b + tid - 96);
        else if (tid < 224) sL2b[tid - 160] = __ldg(L2b + tid - 160);
    }
    __syncthreads();

    // ---- stage 1: h1 = relu(x @ L1W^T + L1b) -> bufT1 (transposed) ----
    {
        float4 xv = ((const float4*)sX)[lane];
        #pragma unroll
        for (int q = 0; q < 4; q++) {
            int c = c0 + q;
            float4 w = ((const float4*)sL1W)[c];         // broadcast
            float v = fmaf(xv.x, w.x, fmaf(xv.y, w.y,
                      fmaf(xv.z, w.z, fmaf(xv.w, w.w, sL1b[c]))));
            bufT1[c * PADT + lane] = fmaxf(v, 0.f);
        }
    }
    // ---- self term -> sRes ----
    if (tid < N_OBJ) {
        float4 xv = ((const float4*)sX)[tid];
        float hs[4];
        #pragma unroll
        for (int f = 0; f < 4; f++) {
            float4 w = __ldg(((const float4*)S1W) + f);
            hs[f] = fmaxf(xv.x*w.x + xv.y*w.y + xv.z*w.z + xv.w*w.w + __ldg(S1b + f), 0.f);
        }
        float4 s2 = __ldg(((const float4*)S2W) + tid);
        sRes[tid * 2 + 0] = hs[0] * s2.x + hs[1] * s2.y + __ldg(S2b + tid * 2 + 0);
        sRes[tid * 2 + 1] = hs[2] * s2.z + hs[3] * s2.w + __ldg(S2b + tid * 2 + 1);
    }
    __syncthreads();

    // ---- stage 2: h2 = relu(h1 @ L2W^T + L2b) -> bufT2 (transposed) ----
    {
        u64 acc[4];
        #pragma unroll
        for (int q = 0; q < 4; q++) acc[q] = pack2(sL2b[c0 + q], 0.f);
        #pragma unroll
        for (int k4 = 0; k4 < 16; k4++) {
            int kb = k4 * 4;
            float h0 = bufT1[(kb + 0) * PADT + lane];
            float h1 = bufT1[(kb + 1) * PADT + lane];
            float h2 = bufT1[(kb + 2) * PADT + lane];
            float h3 = bufT1[(kb + 3) * PADT + lane];
            u64 h01 = pack2(h0, h1), h23 = pack2(h2, h3);
            #pragma unroll
            for (int q = 0; q < 4; q++) {
                ulonglong2 w = *(const ulonglong2*)&sWL2[(c0 + q) * 64 + kb];  // broadcast
                acc[q] = ffma2(h01, w.x, acc[q]);
                acc[q] = ffma2(h23, w.y, acc[q]);
            }
        }
        #pragma unroll
        for (int q = 0; q < 4; q++) {
            float lo, hi; unpack2(acc[q], lo, hi);
            bufT2[(c0 + q) * PADT + lane] = fmaxf(lo + hi, 0.f);
        }
    }
    __syncthreads();

    // ---- stage 3: a = h2 @ I1W^T -> bufT1 reused ROW-MAJOR a[obj][PADF] ----
    {
        u64 acc[4] = {0, 0, 0, 0};
        #pragma unroll
        for (int k4 = 0; k4 < 16; k4++) {
            int kb = k4 * 4;
            float h0 = bufT2[(kb + 0) * PADT + lane];
            float h1 = bufT2[(kb + 1) * PADT + lane];
            float h2 = bufT2[(kb + 2) * PADT + lane];
            float h3 = bufT2[(kb + 3) * PADT + lane];
            u64 h01 = pack2(h0, h1), h23 = pack2(h2, h3);
            #pragma unroll
            for (int q = 0; q < 4; q++) {
                ulonglong2 w = *(const ulonglong2*)&sWI1[(c0 + q) * 64 + kb];
                acc[q] = ffma2(h01, w.x, acc[q]);
                acc[q] = ffma2(h23, w.y, acc[q]);
            }
        }
        float4 o; float lo, hi;
        unpack2(acc[0], lo, hi); o.x = lo + hi;
        unpack2(acc[1], lo, hi); o.y = lo + hi;
        unpack2(acc[2], lo, hi); o.z = lo + hi;
        unpack2(acc[3], lo, hi); o.w = lo + hi;
        // lane = object, c0 aligned to 4 -> conflict-free STS.128
        *(float4*)&bufT1[lane * PADF + c0] = o;
    }
    __syncthreads();

    // ---- pair stage: thread = one i<j pair; writes sPair (no atomics) ----
    if (tid < NPAIR) {
        int i = 0, rem = tid;
        while (rem >= 31 - i) { rem -= 31 - i; ++i; }
        int j = i + 1 + rem;

        const float4* ai = (const float4*)&bufT1[i * PADF];
        const float4* aj = (const float4*)&bufT1[j * PADF];

        u64 p01 = 0, p23 = 0, p45 = 0, p67 = 0;
        #pragma unroll
        for (int k4 = 0; k4 < 16; k4++) {
            float4 av = ai[k4], bv = aj[k4];       // bcast + conflict-free
            float t0 = tanh_fast(av.x - bv.x);
            float t1 = tanh_fast(av.y - bv.y);
            float t2 = tanh_fast(av.z - bv.z);
            float t3 = tanh_fast(av.w - bv.w);
            int hb = k4 * 4;
            #pragma unroll
            for (int u = 0; u < 4; u++) {
                float t = (u == 0) ? t0 : (u == 1) ? t1 : (u == 2) ? t2 : t3;
                u64 tt = pack2(t, t);
                const ulonglong2* wp = (const ulonglong2*)&sI2[(hb + u) * 8];
                ulonglong2 wa = wp[0], wb = wp[1];  // broadcast
                p01 = ffma2(tt, wa.x, p01);
                p23 = ffma2(tt, wa.y, p23);
                p45 = ffma2(tt, wb.x, p45);
                p67 = ffma2(tt, wb.y, p67);
            }
        }
        float t[8];
        unpack2(p01, t[0], t[1]); unpack2(p23, t[2], t[3]);
        unpack2(p45, t[4], t[5]); unpack2(p67, t[6], t[7]);
        #pragma unroll
        for (int f = 0; f < 8; f++) t[f] = tanh_exact(t[f]);

        int idx_ij = i * 31 + (j - 1);
        int idx_ji = j * 31 + i;
        float4 gi0 = __ldg((const float4*)(I3 + idx_ij * 8));
        float4 gi1 = __ldg((const float4*)(I3 + idx_ij * 8) + 1);
        float4 gj0 = __ldg((const float4*)(I3 + idx_ji * 8));
        float4 gj1 = __ldg((const float4*)(I3 + idx_ji * 8) + 1);

        float4 res;
        res.x = t[0]*gi0.x + t[1]*gi0.y + t[2]*gi0.z + t[3]*gi0.w;   // -> object i, out 0
        res.y = t[4]*gi1.x + t[5]*gi1.y + t[6]*gi1.z + t[7]*gi1.w;   // -> object i, out 1
        res.z = -(t[0]*gj0.x + t[1]*gj0.y + t[2]*gj0.z + t[3]*gj0.w); // -> object j, out 0
        res.w = -(t[4]*gj1.x + t[5]*gj1.y + t[6]*gj1.z + t[7]*gj1.w); // -> object j, out 1
        ((float4*)sPair)[tid] = res;               // conflict-free STS.128
    }
    __syncthreads();

    // ---- deterministic reduction + output: thread o sums its 31 terms ----
    if (tid < N_OBJ) {
        const int o = tid;
        float a0 = sRes[o * 2 + 0], a1 = sRes[o * 2 + 1];
        const float2* sp2 = (const float2*)sPair;   // [p][2]: {ci, cj} halves
        int rb = o * 31 - ((o * (o - 1)) >> 1);     // rowbase(o)
        for (int j = o + 1; j < N_OBJ; j++) {
            float2 v = sp2[(rb + j - o - 1) * 2 + 0];
            a0 += v.x; a1 += v.y;
        }
        for (int k = 0; k < o; k++) {
            int p = k * 31 - ((k * (k - 1)) >> 1) + (o - k - 1);
            float2 v = sp2[p * 2 + 1];
            a0 += v.x; a1 += v.y;
        }
        float2 r; r.x = a0; r.y = a1;
        ((float2*)out)[s * N_OBJ + o] = r;
    }
}

extern "C" void kernel_launch(void* const* d_in, const int* in_sizes, int n_in,
                              void* d_out, int out_size) {
    const float* inputs = (const float*)d_in[0];
    const float* L1W    = (const float*)d_in[1];
    const float* L1b    = (const float*)d_in[2];
    const float* L2W    = (const float*)d_in[3];
    const float* L2b    = (const float*)d_in[4];
    const float* I1W    = (const float*)d_in[5];
    const float* I2W    = (const float*)d_in[6];
    const float* I3     = (const float*)d_in[7];
    const float* S1W    = (const float*)d_in[8];
    const float* S1b    = (const float*)d_in[9];
    const float* S2W    = (const float*)d_in[10];
    const float* S2b    = (const float*)d_in[11];
    float* out = (float*)d_out;

    magnet_main<<<S_TOT, 512>>>(inputs, L1W, L1b, L2W, L2b,
                                I1W, I2W, I3, S1W, S1b, S2W, S2b, out);
}

// round 6
// speedup vs baseline: 9.8833x; 1.1905x over previous
#include <cuda_runtime.h>

#define S_TOT 4096
#define N_OBJ 32
#define H_D   64
#define PADT  35   // transposed stride (scalar lane reads conflict-free)
#define PADF  68   // row-major stride (float4 reads/writes conflict-free)
#define NPAIR 496

typedef unsigned long long u64;

__device__ __forceinline__ u64 pack2(float lo, float hi) {
    u64 r; asm("mov.b64 %0, {%1, %2};" : "=l"(r) : "f"(lo), "f"(hi)); return r;
}
__device__ __forceinline__ void unpack2(u64 v, float& lo, float& hi) {
    asm("mov.b64 {%0, %1}, %2;" : "=f"(lo), "=f"(hi) : "l"(v));
}
__device__ __forceinline__ u64 ffma2(u64 a, u64 b, u64 c) {
    u64 d; asm("fma.rn.f32x2 %0, %1, %2, %3;" : "=l"(d) : "l"(a), "l"(b), "l"(c)); return d;
}
__device__ __forceinline__ float tanh_fast(float x) {   // 1 MUFU
    float y; asm("tanh.approx.f32 %0, %1;" : "=f"(y) : "f"(x)); return y;
}
__device__ __forceinline__ float tanh_exact(float x) {
    float e = __expf(2.f * x);
    return 1.f - __fdividef(2.f, e + 1.f);
}

__global__ __launch_bounds__(256, 3)
void magnet_main(const float* __restrict__ X,     // [S,32,4]
                 const float* __restrict__ L1W,   // [64,4]
                 const float* __restrict__ L1b,   // [64]
                 const float* __restrict__ L2W,   // [64,64]
                 const float* __restrict__ L2b,   // [64]
                 const float* __restrict__ I1W,   // [64,64]
                 const float* __restrict__ I2W,   // [8,64]
                 const float* __restrict__ I3,    // [992,2,4]
                 const float* __restrict__ S1W,   // [4,4]
                 const float* __restrict__ S1b,   // [4]
                 const float* __restrict__ S2W,   // [32,2,2]
                 const float* __restrict__ S2b,   // [32,2]
                 float* __restrict__ out)         // [S,32,2]
{
    __shared__ float bufT1[H_D * PADT];                // h1 transposed; reused as row-major a[i][PADF]
    __shared__ float bufT2[H_D * PADT];                // h2 transposed
    __shared__ __align__(16) float sWL2[H_D * H_D];    // L2W row-major [c][k]
    __shared__ __align__(16) float sWI1[H_D * H_D];    // I1W row-major [c][k]
    __shared__ __align__(16) float sI2[H_D * 8];       // [h][f]
    __shared__ __align__(16) float sPair[NPAIR * 4];   // per-pair (ci0,ci1,cj0,cj1)
    __shared__ __align__(16) float sX[N_OBJ * 4];
    __shared__ __align__(16) float sL1W[H_D * 4];
    __shared__ float sL1b[H_D];
    __shared__ float sL2b[H_D];
    __shared__ float sRes[N_OBJ * 2];

    const int tid  = threadIdx.x;
    const int s    = blockIdx.x;
    const int wS   = tid >> 5;       // warp 0..7
    const int lane = tid & 31;       // = object in encoder stages
    const int c0   = wS * 8;         // 8 channels owned by this warp (warp-uniform)

    // ---- staging ----
    {
        const float4* W2 = (const float4*)L2W;
        const float4* W1 = (const float4*)I1W;
        #pragma unroll
        for (int q = 0; q < 4; q++) {
            ((float4*)sWL2)[tid + q * 256] = __ldg(W2 + tid + q * 256);
            ((float4*)sWI1)[tid + q * 256] = __ldg(W1 + tid + q * 256);
        }
        #pragma unroll
        for (int e = 0; e < 2; e++) {                 // sI2[h][f] = I2W[f][h]
            int idx = tid + e * 256;
            int h = idx >> 3, f = idx & 7;
            sI2[idx] = __ldg(I2W + f * 64 + h);
        }
        if (tid < 32)       ((float4*)sX)[tid]        = __ldg(((const float4*)X) + s * 32 + tid);
        else if (tid < 96)  ((float4*)sL1W)[tid - 32] = __ldg(((const float4*)L1W) + (tid - 32));
        else if (tid < 160) sL1b[tid - 96]  = __ldg(L1b + tid - 96);
        else if (tid < 224) sL2b[tid - 160] = __ldg(L2b + tid - 160);
    }
    __syncthreads();

    // ---- stage 1: h1 = relu(x @ L1W^T + L1b) -> bufT1 (transposed) ----
    {
        float4 xv = ((const float4*)sX)[lane];
        #pragma unroll
        for (int q = 0; q < 8; q++) {
            int c = c0 + q;
            float4 w = ((const float4*)sL1W)[c];         // broadcast
            float v = fmaf(xv.x, w.x, fmaf(xv.y, w.y,
                      fmaf(xv.z, w.z, fmaf(xv.w, w.w, sL1b[c]))));
            bufT1[c * PADT + lane] = fmaxf(v, 0.f);
        }
    }
    // ---- self term -> sRes ----
    if (tid < N_OBJ) {
        float4 xv = ((const float4*)sX)[tid];
        float hs[4];
        #pragma unroll
        for (int f = 0; f < 4; f++) {
            float4 w = __ldg(((const float4*)S1W) + f);
            hs[f] = fmaxf(xv.x*w.x + xv.y*w.y + xv.z*w.z + xv.w*w.w + __ldg(S1b + f), 0.f);
        }
        float4 s2 = __ldg(((const float4*)S2W) + tid);
        sRes[tid * 2 + 0] = hs[0] * s2.x + hs[1] * s2.y + __ldg(S2b + tid * 2 + 0);
        sRes[tid * 2 + 1] = hs[2] * s2.z + hs[3] * s2.w + __ldg(S2b + tid * 2 + 1);
    }
    __syncthreads();

    // ---- stage 2: h2 = relu(h1 @ L2W^T + L2b) -> bufT2 (transposed) ----
    {
        u64 acc[8];
        #pragma unroll
        for (int q = 0; q < 8; q++) acc[q] = pack2(sL2b[c0 + q], 0.f);
        #pragma unroll
        for (int k4 = 0; k4 < 16; k4++) {
            int kb = k4 * 4;
            float h0 = bufT1[(kb + 0) * PADT + lane];
            float h1 = bufT1[(kb + 1) * PADT + lane];
            float h2 = bufT1[(kb + 2) * PADT + lane];
            float h3 = bufT1[(kb + 3) * PADT + lane];
            u64 h01 = pack2(h0, h1), h23 = pack2(h2, h3);
            #pragma unroll
            for (int q = 0; q < 8; q++) {
                ulonglong2 w = *(const ulonglong2*)&sWL2[(c0 + q) * 64 + kb];  // broadcast
                acc[q] = ffma2(h01, w.x, acc[q]);
                acc[q] = ffma2(h23, w.y, acc[q]);
            }
        }
        #pragma unroll
        for (int q = 0; q < 8; q++) {
            float lo, hi; unpack2(acc[q], lo, hi);
            bufT2[(c0 + q) * PADT + lane] = fmaxf(lo + hi, 0.f);
        }
    }
    __syncthreads();

    // ---- stage 3: a = h2 @ I1W^T -> bufT1 reused ROW-MAJOR a[obj][PADF] ----
    {
        u64 acc[8] = {0,0,0,0,0,0,0,0};
        #pragma unroll
        for (int k4 = 0; k4 < 16; k4++) {
            int kb = k4 * 4;
            float h0 = bufT2[(kb + 0) * PADT + lane];
            float h1 = bufT2[(kb + 1) * PADT + lane];
            float h2 = bufT2[(kb + 2) * PADT + lane];
            float h3 = bufT2[(kb + 3) * PADT + lane];
            u64 h01 = pack2(h0, h1), h23 = pack2(h2, h3);
            #pragma unroll
            for (int q = 0; q < 8; q++) {
                ulonglong2 w = *(const ulonglong2*)&sWI1[(c0 + q) * 64 + kb];
                acc[q] = ffma2(h01, w.x, acc[q]);
                acc[q] = ffma2(h23, w.y, acc[q]);
            }
        }
        // write two float4s: lane=object, channels c0..c0+7
        float4 o; float lo, hi;
        unpack2(acc[0], lo, hi); o.x = lo + hi;
        unpack2(acc[1], lo, hi); o.y = lo + hi;
        unpack2(acc[2], lo, hi); o.z = lo + hi;
        unpack2(acc[3], lo, hi); o.w = lo + hi;
        *(float4*)&bufT1[lane * PADF + c0] = o;
        unpack2(acc[4], lo, hi); o.x = lo + hi;
        unpack2(acc[5], lo, hi); o.y = lo + hi;
        unpack2(acc[6], lo, hi); o.z = lo + hi;
        unpack2(acc[7], lo, hi); o.w = lo + hi;
        *(float4*)&bufT1[lane * PADF + c0 + 4] = o;
    }
    __syncthreads();

    // ---- pair stage: thread handles TWO i<j pairs (weight bcasts amortized) ----
    if (tid < NPAIR / 2) {
        int i1, j1, i2, j2;
        {
            int p = 2 * tid, i = 0, rem = p;
            while (rem >= 31 - i) { rem -= 31 - i; ++i; }
            i1 = i; j1 = i + 1 + rem;
            p = 2 * tid + 1; i = 0; rem = p;
            while (rem >= 31 - i) { rem -= 31 - i; ++i; }
            i2 = i; j2 = i + 1 + rem;
        }
        const float4* ai1 = (const float4*)&bufT1[i1 * PADF];
        const float4* aj1 = (const float4*)&bufT1[j1 * PADF];
        const float4* ai2 = (const float4*)&bufT1[i2 * PADF];
        const float4* aj2 = (const float4*)&bufT1[j2 * PADF];

        u64 A01=0,A23=0,A45=0,A67=0, B01=0,B23=0,B45=0,B67=0;
        #pragma unroll
        for (int k4 = 0; k4 < 16; k4++) {
            float4 x1 = ai1[k4], y1 = aj1[k4];
            float4 x2 = ai2[k4], y2 = aj2[k4];
            float ta[4], tb[4];
            ta[0] = tanh_fast(x1.x - y1.x); ta[1] = tanh_fast(x1.y - y1.y);
            ta[2] = tanh_fast(x1.z - y1.z); ta[3] = tanh_fast(x1.w - y1.w);
            tb[0] = tanh_fast(x2.x - y2.x); tb[1] = tanh_fast(x2.y - y2.y);
            tb[2] = tanh_fast(x2.z - y2.z); tb[3] = tanh_fast(x2.w - y2.w);
            int hb = k4 * 4;
            #pragma unroll
            for (int u = 0; u < 4; u++) {
                const ulonglong2* wp = (const ulonglong2*)&sI2[(hb + u) * 8];
                ulonglong2 wa = wp[0], wb = wp[1];     // broadcast, feeds both pairs
                u64 pa = pack2(ta[u], ta[u]);
                u64 pb = pack2(tb[u], tb[u]);
                A01 = ffma2(pa, wa.x, A01); A23 = ffma2(pa, wa.y, A23);
                A45 = ffma2(pa, wb.x, A45); A67 = ffma2(pa, wb.y, A67);
                B01 = ffma2(pb, wa.x, B01); B23 = ffma2(pb, wa.y, B23);
                B45 = ffma2(pb, wb.x, B45); B67 = ffma2(pb, wb.y, B67);
            }
        }
        // epilogue per pair
        #pragma unroll
        for (int pp = 0; pp < 2; pp++) {
            float t[8];
            if (pp == 0) {
                unpack2(A01, t[0], t[1]); unpack2(A23, t[2], t[3]);
                unpack2(A45, t[4], t[5]); unpack2(A67, t[6], t[7]);
            } else {
                unpack2(B01, t[0], t[1]); unpack2(B23, t[2], t[3]);
                unpack2(B45, t[4], t[5]); unpack2(B67, t[6], t[7]);
            }
            #pragma unroll
            for (int f = 0; f < 8; f++) t[f] = tanh_exact(t[f]);

            int i = pp ? i2 : i1, j = pp ? j2 : j1;
            int idx_ij = i * 31 + (j - 1);
            int idx_ji = j * 31 + i;
            float4 gi0 = __ldg((const float4*)(I3 + idx_ij * 8));
            float4 gi1 = __ldg((const float4*)(I3 + idx_ij * 8) + 1);
            float4 gj0 = __ldg((const float4*)(I3 + idx_ji * 8));
            float4 gj1 = __ldg((const float4*)(I3 + idx_ji * 8) + 1);

            float4 res;
            res.x = t[0]*gi0.x + t[1]*gi0.y + t[2]*gi0.z + t[3]*gi0.w;
            res.y = t[4]*gi1.x + t[5]*gi1.y + t[6]*gi1.z + t[7]*gi1.w;
            res.z = -(t[0]*gj0.x + t[1]*gj0.y + t[2]*gj0.z + t[3]*gj0.w);
            res.w = -(t[4]*gj1.x + t[5]*gj1.y + t[6]*gj1.z + t[7]*gj1.w);
            ((float4*)sPair)[2 * tid + pp] = res;
        }
    }
    __syncthreads();

    // ---- deterministic reduction + output ----
    if (tid < N_OBJ) {
        const int o = tid;
        float a0 = sRes[o * 2 + 0], a1 = sRes[o * 2 + 1];
        const float2* sp2 = (const float2*)sPair;
        int rb = o * 31 - ((o * (o - 1)) >> 1);
        for (int j = o + 1; j < N_OBJ; j++) {
            float2 v = sp2[(rb + j - o - 1) * 2 + 0];
            a0 += v.x; a1 += v.y;
        }
        for (int k = 0; k < o; k++) {
            int p = k * 31 - ((k * (k - 1)) >> 1) + (o - k - 1);
            float2 v = sp2[p * 2 + 1];
            a0 += v.x; a1 += v.y;
        }
        float2 r; r.x = a0; r.y = a1;
        ((float2*)out)[s * N_OBJ + o] = r;
    }
}

extern "C" void kernel_launch(void* const* d_in, const int* in_sizes, int n_in,
                              void* d_out, int out_size) {
    const float* inputs = (const float*)d_in[0];
    const float* L1W    = (const float*)d_in[1];
    const float* L1b    = (const float*)d_in[2];
    const float* L2W    = (const float*)d_in[3];
    const float* L2b    = (const float*)d_in[4];
    const float* I1W    = (const float*)d_in[5];
    const float* I2W    = (const float*)d_in[6];
    const float* I3     = (const float*)d_in[7];
    const float* S1W    = (const float*)d_in[8];
    const float* S1b    = (const float*)d_in[9];
    const float* S2W    = (const float*)d_in[10];
    const float* S2b    = (const float*)d_in[11];
    float* out = (float*)d_out;

    magnet_main<<<S_TOT, 256>>>(inputs, L1W, L1b, L2W, L2b,
                                I1W, I2W, I3, S1W, S1b, S2W, S2b, out);
}

// round 7
// speedup vs baseline: 10.2293x; 1.0350x over previous
#include <cuda_runtime.h>

#define S_TOT 4096
#define N_OBJ 32
#define H_D   64
#define PADT  35   // transposed stride (scalar lane reads conflict-free)
#define PADF  68   // row-major stride (float4 reads/writes conflict-free)
#define NPAIR 496

typedef unsigned long long u64;

__device__ __forceinline__ u64 pack2(float lo, float hi) {
    u64 r; asm("mov.b64 %0, {%1, %2};" : "=l"(r) : "f"(lo), "f"(hi)); return r;
}
__device__ __forceinline__ void unpack2(u64 v, float& lo, float& hi) {
    asm("mov.b64 {%0, %1}, %2;" : "=f"(lo), "=f"(hi) : "l"(v));
}
__device__ __forceinline__ u64 ffma2(u64 a, u64 b, u64 c) {
    u64 d; asm("fma.rn.f32x2 %0, %1, %2, %3;" : "=l"(d) : "l"(a), "l"(b), "l"(c)); return d;
}
__device__ __forceinline__ float tanh_fast(float x) {   // 1 MUFU
    float y; asm("tanh.approx.f32 %0, %1;" : "=f"(y) : "f"(x)); return y;
}
__device__ __forceinline__ float tanh_exact(float x) {
    float e = __expf(2.f * x);
    return 1.f - __fdividef(2.f, e + 1.f);
}

__global__ __launch_bounds__(256, 4)
void magnet_main(const float* __restrict__ X,     // [S,32,4]
                 const float* __restrict__ L1W,   // [64,4]
                 const float* __restrict__ L1b,   // [64]
                 const float* __restrict__ L2W,   // [64,64]
                 const float* __restrict__ L2b,   // [64]
                 const float* __restrict__ I1W,   // [64,64]
                 const float* __restrict__ I2W,   // [8,64]
                 const float* __restrict__ I3,    // [992,2,4]
                 const float* __restrict__ S1W,   // [4,4]
                 const float* __restrict__ S1b,   // [4]
                 const float* __restrict__ S2W,   // [32,2,2]
                 const float* __restrict__ S2b,   // [32,2]
                 float* __restrict__ out)         // [S,32,2]
{
    __shared__ float bufT1[H_D * PADT];                // h1 transposed; reused as row-major a[i][PADF]
    // bufT2 (h2 transposed, dies after stage 3) aliased with sPair (born in pair stage)
    __shared__ __align__(16) float bufT2_sPair[H_D * PADT > NPAIR * 4 ? H_D * PADT : NPAIR * 4];
    __shared__ __align__(16) float sWL2[H_D * H_D];    // L2W row-major [c][k]
    __shared__ __align__(16) float sWI1[H_D * H_D];    // I1W row-major [c][k]
    __shared__ __align__(16) float sI2[H_D * 8];       // [h][f]
    __shared__ __align__(16) float sX[N_OBJ * 4];
    __shared__ __align__(16) float sL1W[H_D * 4];
    __shared__ float sL1b[H_D];
    __shared__ float sL2b[H_D];
    __shared__ float sRes[N_OBJ * 2];

    float* bufT2 = bufT2_sPair;
    float* sPair = bufT2_sPair;

    const int tid  = threadIdx.x;
    const int s    = blockIdx.x;
    const int wS   = tid >> 5;       // warp 0..7
    const int lane = tid & 31;       // = object in encoder stages
    const int c0   = wS * 8;         // 8 channels owned by this warp (warp-uniform)

    // ---- staging ----
    {
        const float4* W2 = (const float4*)L2W;
        const float4* W1 = (const float4*)I1W;
        #pragma unroll
        for (int q = 0; q < 4; q++) {
            ((float4*)sWL2)[tid + q * 256] = __ldg(W2 + tid + q * 256);
            ((float4*)sWI1)[tid + q * 256] = __ldg(W1 + tid + q * 256);
        }
        #pragma unroll
        for (int e = 0; e < 2; e++) {                 // sI2[h][f] = I2W[f][h]
            int idx = tid + e * 256;
            int h = idx >> 3, f = idx & 7;
            sI2[idx] = __ldg(I2W + f * 64 + h);
        }
        if (tid < 32)       ((float4*)sX)[tid]        = __ldg(((const float4*)X) + s * 32 + tid);
        else if (tid < 96)  ((float4*)sL1W)[tid - 32] = __ldg(((const float4*)L1W) + (tid - 32));
        else if (tid < 160) sL1b[tid - 96]  = __ldg(L1b + tid - 96);
        else if (tid < 224) sL2b[tid - 160] = __ldg(L2b + tid - 160);
    }
    __syncthreads();

    // ---- stage 1: h1 = relu(x @ L1W^T + L1b) -> bufT1 (transposed) ----
    {
        float4 xv = ((const float4*)sX)[lane];
        #pragma unroll
        for (int q = 0; q < 8; q++) {
            int c = c0 + q;
            float4 w = ((const float4*)sL1W)[c];         // broadcast
            float v = fmaf(xv.x, w.x, fmaf(xv.y, w.y,
                      fmaf(xv.z, w.z, fmaf(xv.w, w.w, sL1b[c]))));
            bufT1[c * PADT + lane] = fmaxf(v, 0.f);
        }
    }
    // ---- self term -> sRes ----
    if (tid < N_OBJ) {
        float4 xv = ((const float4*)sX)[tid];
        float hs[4];
        #pragma unroll
        for (int f = 0; f < 4; f++) {
            float4 w = __ldg(((const float4*)S1W) + f);
            hs[f] = fmaxf(xv.x*w.x + xv.y*w.y + xv.z*w.z + xv.w*w.w + __ldg(S1b + f), 0.f);
        }
        float4 s2 = __ldg(((const float4*)S2W) + tid);
        sRes[tid * 2 + 0] = hs[0] * s2.x + hs[1] * s2.y + __ldg(S2b + tid * 2 + 0);
        sRes[tid * 2 + 1] = hs[2] * s2.z + hs[3] * s2.w + __ldg(S2b + tid * 2 + 1);
    }
    __syncthreads();

    // ---- stage 2: h2 = relu(h1 @ L2W^T + L2b) -> bufT2 (transposed) ----
    {
        u64 acc[8];
        #pragma unroll
        for (int q = 0; q < 8; q++) acc[q] = pack2(sL2b[c0 + q], 0.f);
        #pragma unroll
        for (int k4 = 0; k4 < 16; k4++) {
            int kb = k4 * 4;
            float h0 = bufT1[(kb + 0) * PADT + lane];
            float h1 = bufT1[(kb + 1) * PADT + lane];
            float h2 = bufT1[(kb + 2) * PADT + lane];
            float h3 = bufT1[(kb + 3) * PADT + lane];
            u64 h01 = pack2(h0, h1), h23 = pack2(h2, h3);
            #pragma unroll
            for (int q = 0; q < 8; q++) {
                ulonglong2 w = *(const ulonglong2*)&sWL2[(c0 + q) * 64 + kb];  // broadcast
                acc[q] = ffma2(h01, w.x, acc[q]);
                acc[q] = ffma2(h23, w.y, acc[q]);
            }
        }
        #pragma unroll
        for (int q = 0; q < 8; q++) {
            float lo, hi; unpack2(acc[q], lo, hi);
            bufT2[(c0 + q) * PADT + lane] = fmaxf(lo + hi, 0.f);
        }
    }
    __syncthreads();

    // ---- stage 3: a = h2 @ I1W^T -> bufT1 reused ROW-MAJOR a[obj][PADF] ----
    {
        u64 acc[8] = {0,0,0,0,0,0,0,0};
        #pragma unroll
        for (int k4 = 0; k4 < 16; k4++) {
            int kb = k4 * 4;
            float h0 = bufT2[(kb + 0) * PADT + lane];
            float h1 = bufT2[(kb + 1) * PADT + lane];
            float h2 = bufT2[(kb + 2) * PADT + lane];
            float h3 = bufT2[(kb + 3) * PADT + lane];
            u64 h01 = pack2(h0, h1), h23 = pack2(h2, h3);
            #pragma unroll
            for (int q = 0; q < 8; q++) {
                ulonglong2 w = *(const ulonglong2*)&sWI1[(c0 + q) * 64 + kb];
                acc[q] = ffma2(h01, w.x, acc[q]);
                acc[q] = ffma2(h23, w.y, acc[q]);
            }
        }
        float4 o; float lo, hi;
        unpack2(acc[0], lo, hi); o.x = lo + hi;
        unpack2(acc[1], lo, hi); o.y = lo + hi;
        unpack2(acc[2], lo, hi); o.z = lo + hi;
        unpack2(acc[3], lo, hi); o.w = lo + hi;
        *(float4*)&bufT1[lane * PADF + c0] = o;
        unpack2(acc[4], lo, hi); o.x = lo + hi;
        unpack2(acc[5], lo, hi); o.y = lo + hi;
        unpack2(acc[6], lo, hi); o.z = lo + hi;
        unpack2(acc[7], lo, hi); o.w = lo + hi;
        *(float4*)&bufT1[lane * PADF + c0 + 4] = o;
    }
    __syncthreads();

    // ---- pair stage: 256 units, each = (i, j0, j0+1), both pairs share a_i ----
    // units per row i: (32-i)>>1; total = 256 exactly.
    {
        int i = 0, base = 0;
        while (tid >= base + ((32 - i) >> 1)) { base += (32 - i) >> 1; ++i; }
        const int u  = tid - base;
        const int j0 = i + 1 + 2 * u;
        const int j1 = j0 + 1;
        const bool has2 = (j1 < N_OBJ);

        const float4* ai  = (const float4*)&bufT1[i * PADF];
        const float4* aj0 = (const float4*)&bufT1[j0 * PADF];
        const float4* aj1 = (const float4*)&bufT1[(has2 ? j1 : j0) * PADF];

        u64 A01=0,A23=0,A45=0,A67=0, B01=0,B23=0,B45=0,B67=0;
        #pragma unroll
        for (int k4 = 0; k4 < 16; k4++) {
            float4 xv = ai[k4];                    // shared between both pairs
            float4 y0 = aj0[k4], y1 = aj1[k4];
            float ta[4], tb[4];
            ta[0] = tanh_fast(xv.x - y0.x); ta[1] = tanh_fast(xv.y - y0.y);
            ta[2] = tanh_fast(xv.z - y0.z); ta[3] = tanh_fast(xv.w - y0.w);
            tb[0] = tanh_fast(xv.x - y1.x); tb[1] = tanh_fast(xv.y - y1.y);
            tb[2] = tanh_fast(xv.z - y1.z); tb[3] = tanh_fast(xv.w - y1.w);
            int hb = k4 * 4;
            #pragma unroll
            for (int v = 0; v < 4; v++) {
                const ulonglong2* wp = (const ulonglong2*)&sI2[(hb + v) * 8];
                ulonglong2 wa = wp[0], wb = wp[1];     // broadcast, feeds both pairs
                u64 pa = pack2(ta[v], ta[v]);
                u64 pb = pack2(tb[v], tb[v]);
                A01 = ffma2(pa, wa.x, A01); A23 = ffma2(pa, wa.y, A23);
                A45 = ffma2(pa, wb.x, A45); A67 = ffma2(pa, wb.y, A67);
                B01 = ffma2(pb, wa.x, B01); B23 = ffma2(pb, wa.y, B23);
                B45 = ffma2(pb, wb.x, B45); B67 = ffma2(pb, wb.y, B67);
            }
        }
        __syncthreads();   // all reads of bufT1/bufT2 done; sPair may now overwrite

        #pragma unroll
        for (int pp = 0; pp < 2; pp++) {
            if (pp == 1 && !has2) break;
            float t[8];
            if (pp == 0) {
                unpack2(A01, t[0], t[1]); unpack2(A23, t[2], t[3]);
                unpack2(A45, t[4], t[5]); unpack2(A67, t[6], t[7]);
            } else {
                unpack2(B01, t[0], t[1]); unpack2(B23, t[2], t[3]);
                unpack2(B45, t[4], t[5]); unpack2(B67, t[6], t[7]);
            }
            #pragma unroll
            for (int f = 0; f < 8; f++) t[f] = tanh_exact(t[f]);

            int j = pp ? j1 : j0;
            int idx_ij = i * 31 + (j - 1);          // dense (i, j!=i) row-major
            int idx_ji = j * 31 + i;
            float4 gi0 = __ldg((const float4*)(I3 + idx_ij * 8));
            float4 gi1 = __ldg((const float4*)(I3 + idx_ij * 8) + 1);
            float4 gj0 = __ldg((const float4*)(I3 + idx_ji * 8));
            float4 gj1 = __ldg((const float4*)(I3 + idx_ji * 8) + 1);

            float4 res;
            res.x = t[0]*gi0.x + t[1]*gi0.y + t[2]*gi0.z + t[3]*gi0.w;
            res.y = t[4]*gi1.x + t[5]*gi1.y + t[6]*gi1.z + t[7]*gi1.w;
            res.z = -(t[0]*gj0.x + t[1]*gj0.y + t[2]*gj0.z + t[3]*gj0.w);
            res.w = -(t[4]*gj1.x + t[5]*gj1.y + t[6]*gj1.z + t[7]*gj1.w);
            // upper-triangle linear index rb(i) + (j-i-1)
            int p = i * 31 - ((i * (i - 1)) >> 1) + (j - i - 1);
            ((float4*)sPair)[p] = res;
        }
    }
    __syncthreads();

    // ---- deterministic reduction + output ----
    if (tid < N_OBJ) {
        const int o = tid;
        float a0 = sRes[o * 2 + 0], a1 = sRes[o * 2 + 1];
        const float2* sp2 = (const float2*)sPair;
        int rb = o * 31 - ((o * (o - 1)) >> 1);
        for (int j = o + 1; j < N_OBJ; j++) {
            float2 v = sp2[(rb + j - o - 1) * 2 + 0];
            a0 += v.x; a1 += v.y;
        }
        for (int k = 0; k < o; k++) {
            int p = k * 31 - ((k * (k - 1)) >> 1) + (o - k - 1);
            float2 v = sp2[p * 2 + 1];
            a0 += v.x; a1 += v.y;
        }
        float2 r; r.x = a0; r.y = a1;
        ((float2*)out)[s * N_OBJ + o] = r;
    }
}

extern "C" void kernel_launch(void* const* d_in, const int* in_sizes, int n_in,
                              void* d_out, int out_size) {
    const float* inputs = (const float*)d_in[0];
    const float* L1W    = (const float*)d_in[1];
    const float* L1b    = (const float*)d_in[2];
    const float* L2W    = (const float*)d_in[3];
    const float* L2b    = (const float*)d_in[4];
    const float* I1W    = (const float*)d_in[5];
    const float* I2W    = (const float*)d_in[6];
    const float* I3     = (const float*)d_in[7];
    const float* S1W    = (const float*)d_in[8];
    const float* S1b    = (const float*)d_in[9];
    const float* S2W    = (const float*)d_in[10];
    const float* S2b    = (const float*)d_in[11];
    float* out = (float*)d_out;

    magnet_main<<<S_TOT, 256>>>(inputs, L1W, L1b, L2W, L2b,
                                I1W, I2W, I3, S1W, S1b, S2W, S2b, out);
}

// round 8
// speedup vs baseline: 15.5074x; 1.5160x over previous
#include <cuda_runtime.h>

#define S_TOT 4096
#define N_OBJ 32
#define H_D   64
#define PT    35   // transposed stride (scalar lane reads conflict-free)
#define PA    68   // row-major stride for a (float4 conflict-free; PA/4=17)
#define NPAIR 496

typedef unsigned long long u64;

__device__ __forceinline__ u64 pack2(float lo, float hi) {
    u64 r; asm("mov.b64 %0, {%1, %2};" : "=l"(r) : "f"(lo), "f"(hi)); return r;
}
__device__ __forceinline__ void unpack2(u64 v, float& lo, float& hi) {
    asm("mov.b64 {%0, %1}, %2;" : "=f"(lo), "=f"(hi) : "l"(v));
}
__device__ __forceinline__ u64 ffma2(u64 a, u64 b, u64 c) {
    u64 d; asm("fma.rn.f32x2 %0, %1, %2, %3;" : "=l"(d) : "l"(a), "l"(b), "l"(c)); return d;
}
__device__ __forceinline__ float tanh_fast(float x) {   // 1 MUFU
    float y; asm("tanh.approx.f32 %0, %1;" : "=f"(y) : "f"(x)); return y;
}
__device__ __forceinline__ float tanh_exact(float x) {
    float e = __expf(2.f * x);
    return 1.f - __fdividef(2.f, e + 1.f);
}

__global__ __launch_bounds__(256, 3)
void magnet_main(const float* __restrict__ X,     // [S,32,4]
                 const float* __restrict__ L1W,   // [64,4]
                 const float* __restrict__ L1b,   // [64]
                 const float* __restrict__ L2W,   // [64,64]
                 const float* __restrict__ L2b,   // [64]
                 const float* __restrict__ I1W,   // [64,64]
                 const float* __restrict__ I2W,   // [8,64]
                 const float* __restrict__ I3,    // [992,2,4]
                 const float* __restrict__ S1W,   // [4,4]
                 const float* __restrict__ S1b,   // [4]
                 const float* __restrict__ S2W,   // [32,2,2]
                 const float* __restrict__ S2b,   // [32,2]
                 float* __restrict__ out)         // [S,32,2]
{
    // 2 samples per block
    __shared__ __align__(16) float bufT1[2 * H_D * PT];       // h1 [s][k][PT]; reused: a [s][obj][PA]
    __shared__ __align__(16) float bufT2_sPair[2 * H_D * PT]; // h2 [s][k][PT]; aliased: sPair [s][496][4]
    __shared__ __align__(16) float sW[H_D * H_D];             // L2W then I1W (row-major [c][k])
    __shared__ __align__(16) float sI2[H_D * 8];              // [h][f]
    __shared__ __align__(16) float sX[2 * N_OBJ * 4];
    __shared__ __align__(16) float sL1W[H_D * 4];
    __shared__ float sL1b[H_D];
    __shared__ float sL2b[H_D];
    __shared__ float sRes[2 * N_OBJ * 2];

    float* bufT2 = bufT2_sPair;
    float* sPair = bufT2_sPair;

    const int tid  = threadIdx.x;
    const int bid  = blockIdx.x;
    const int wS   = tid >> 5;       // warp 0..7
    const int lane = tid & 31;       // = object in encoder stages
    const int c0   = wS * 8;         // 8 channels per warp (warp-uniform)

    // ---- staging ----
    {
        const float4* W2 = (const float4*)L2W;
        #pragma unroll
        for (int q = 0; q < 4; q++)
            ((float4*)sW)[tid + q * 256] = __ldg(W2 + tid + q * 256);
        #pragma unroll
        for (int e = 0; e < 2; e++) {                 // sI2[h][f] = I2W[f][h]
            int idx = tid + e * 256;
            int h = idx >> 3, f = idx & 7;
            sI2[idx] = __ldg(I2W + f * 64 + h);
        }
        if (tid < 64)        ((float4*)sX)[tid]        = __ldg(((const float4*)X) + bid * 64 + tid);
        else if (tid < 128)  ((float4*)sL1W)[tid - 64] = __ldg(((const float4*)L1W) + (tid - 64));
        else if (tid < 192)  sL1b[tid - 128] = __ldg(L1b + tid - 128);
        else                 sL2b[tid - 192] = __ldg(L2b + tid - 192);
    }
    __syncthreads();

    // ---- stage 1: h1 = relu(x @ L1W^T + L1b), both samples -> bufT1 transposed ----
    {
        float4 x0 = ((const float4*)sX)[lane];
        float4 x1 = ((const float4*)sX)[N_OBJ + lane];
        #pragma unroll
        for (int q = 0; q < 8; q++) {
            int c = c0 + q;
            float4 w = ((const float4*)sL1W)[c];         // broadcast (shared by both samples)
            float b = sL1b[c];
            float v0 = fmaf(x0.x, w.x, fmaf(x0.y, w.y, fmaf(x0.z, w.z, fmaf(x0.w, w.w, b))));
            float v1 = fmaf(x1.x, w.x, fmaf(x1.y, w.y, fmaf(x1.z, w.z, fmaf(x1.w, w.w, b))));
            bufT1[c * PT + lane]             = fmaxf(v0, 0.f);
            bufT1[(H_D + c) * PT + lane]     = fmaxf(v1, 0.f);
        }
    }
    // ---- self term (64 threads = 2 samples x 32 obj) -> sRes ----
    if (tid < 64) {
        int o = tid & 31;
        float4 xv = ((const float4*)sX)[tid];
        float hs[4];
        #pragma unroll
        for (int f = 0; f < 4; f++) {
            float4 w = __ldg(((const float4*)S1W) + f);
            hs[f] = fmaxf(xv.x*w.x + xv.y*w.y + xv.z*w.z + xv.w*w.w + __ldg(S1b + f), 0.f);
        }
        float4 s2 = __ldg(((const float4*)S2W) + o);
        sRes[tid * 2 + 0] = hs[0] * s2.x + hs[1] * s2.y + __ldg(S2b + o * 2 + 0);
        sRes[tid * 2 + 1] = hs[2] * s2.z + hs[3] * s2.w + __ldg(S2b + o * 2 + 1);
    }
    __syncthreads();

    // ---- stage 2: h2 = relu(h1 @ L2W^T + L2b), both samples -> bufT2 ----
    {
        u64 acc0[8], acc1[8];
        #pragma unroll
        for (int q = 0; q < 8; q++) { acc0[q] = pack2(sL2b[c0 + q], 0.f); acc1[q] = acc0[q]; }
        #pragma unroll
        for (int k4 = 0; k4 < 16; k4++) {
            int kb = k4 * 4;
            float p0 = bufT1[(kb + 0) * PT + lane];
            float p1 = bufT1[(kb + 1) * PT + lane];
            float p2 = bufT1[(kb + 2) * PT + lane];
            float p3 = bufT1[(kb + 3) * PT + lane];
            float q0 = bufT1[(H_D + kb + 0) * PT + lane];
            float q1 = bufT1[(H_D + kb + 1) * PT + lane];
            float q2 = bufT1[(H_D + kb + 2) * PT + lane];
            float q3 = bufT1[(H_D + kb + 3) * PT + lane];
            u64 hA0 = pack2(p0, p1), hA1 = pack2(p2, p3);
            u64 hB0 = pack2(q0, q1), hB1 = pack2(q2, q3);
            #pragma unroll
            for (int q = 0; q < 8; q++) {
                ulonglong2 w = *(const ulonglong2*)&sW[(c0 + q) * 64 + kb];  // one bcast, 2 samples
                acc0[q] = ffma2(hA0, w.x, acc0[q]); acc0[q] = ffma2(hA1, w.y, acc0[q]);
                acc1[q] = ffma2(hB0, w.x, acc1[q]); acc1[q] = ffma2(hB1, w.y, acc1[q]);
            }
        }
        #pragma unroll
        for (int q = 0; q < 8; q++) {
            float lo, hi;
            unpack2(acc0[q], lo, hi); bufT2[(c0 + q) * PT + lane]       = fmaxf(lo + hi, 0.f);
            unpack2(acc1[q], lo, hi); bufT2[(H_D + c0 + q) * PT + lane] = fmaxf(lo + hi, 0.f);
        }
    }
    __syncthreads();

    // ---- restage: sW <- I1W ----
    {
        const float4* W1 = (const float4*)I1W;
        #pragma unroll
        for (int q = 0; q < 4; q++)
            ((float4*)sW)[tid + q * 256] = __ldg(W1 + tid + q * 256);
    }
    __syncthreads();

    // ---- stage 3: a = h2 @ I1W^T -> bufT1 reused ROW-MAJOR a[s][obj][PA] ----
    {
        u64 acc0[8] = {0,0,0,0,0,0,0,0}, acc1[8] = {0,0,0,0,0,0,0,0};
        #pragma unroll
        for (int k4 = 0; k4 < 16; k4++) {
            int kb = k4 * 4;
            float p0 = bufT2[(kb + 0) * PT + lane];
            float p1 = bufT2[(kb + 1) * PT + lane];
            float p2 = bufT2[(kb + 2) * PT + lane];
            float p3 = bufT2[(kb + 3) * PT + lane];
            float q0 = bufT2[(H_D + kb + 0) * PT + lane];
            float q1 = bufT2[(H_D + kb + 1) * PT + lane];
            float q2 = bufT2[(H_D + kb + 2) * PT + lane];
            float q3 = bufT2[(H_D + kb + 3) * PT + lane];
            u64 hA0 = pack2(p0, p1), hA1 = pack2(p2, p3);
            u64 hB0 = pack2(q0, q1), hB1 = pack2(q2, q3);
            #pragma unroll
            for (int q = 0; q < 8; q++) {
                ulonglong2 w = *(const ulonglong2*)&sW[(c0 + q) * 64 + kb];
                acc0[q] = ffma2(hA0, w.x, acc0[q]); acc0[q] = ffma2(hA1, w.y, acc0[q]);
                acc1[q] = ffma2(hB0, w.x, acc1[q]); acc1[q] = ffma2(hB1, w.y, acc1[q]);
            }
        }
        float4 o; float lo, hi;
        unpack2(acc0[0], lo, hi); o.x = lo + hi;
        unpack2(acc0[1], lo, hi); o.y = lo + hi;
        unpack2(acc0[2], lo, hi); o.z = lo + hi;
        unpack2(acc0[3], lo, hi); o.w = lo + hi;
        *(float4*)&bufT1[lane * PA + c0] = o;
        unpack2(acc0[4], lo, hi); o.x = lo + hi;
        unpack2(acc0[5], lo, hi); o.y = lo + hi;
        unpack2(acc0[6], lo, hi); o.z = lo + hi;
        unpack2(acc0[7], lo, hi); o.w = lo + hi;
        *(float4*)&bufT1[lane * PA + c0 + 4] = o;
        unpack2(acc1[0], lo, hi); o.x = lo + hi;
        unpack2(acc1[1], lo, hi); o.y = lo + hi;
        unpack2(acc1[2], lo, hi); o.z = lo + hi;
        unpack2(acc1[3], lo, hi); o.w = lo + hi;
        *(float4*)&bufT1[(N_OBJ + lane) * PA + c0] = o;
        unpack2(acc1[4], lo, hi); o.x = lo + hi;
        unpack2(acc1[5], lo, hi); o.y = lo + hi;
        unpack2(acc1[6], lo, hi); o.z = lo + hi;
        unpack2(acc1[7], lo, hi); o.w = lo + hi;
        *(float4*)&bufT1[(N_OBJ + lane) * PA + c0 + 4] = o;
    }
    __syncthreads();

    // ---- pair stage: unit = (i, j0, j1), SAME unit for both samples ----
    // j block-split: j0 = i+1+u, j1 = j0+nu -> consecutive j across lanes (conflict-free)
    {
        int i = 0, base = 0;
        while (tid >= base + ((32 - i) >> 1)) { base += (32 - i) >> 1; ++i; }
        const int u  = tid - base;
        const int nu = (32 - i) >> 1;
        const int j0 = i + 1 + u;
        const int j1 = j0 + nu;
        const bool has2 = (j1 <= 31);
        const int j1c = has2 ? j1 : j0;

        const float4* A = (const float4*)bufT1;      // rows of 17 float4
        const float4* ai0  = A + i * 17;
        const float4* aj00 = A + j0 * 17;
        const float4* aj01 = A + j1c * 17;
        const float4* ai1  = A + (N_OBJ + i) * 17;
        const float4* aj10 = A + (N_OBJ + j0) * 17;
        const float4* aj11 = A + (N_OBJ + j1c) * 17;

        u64 P[4][4] = {};   // [s0p0, s0p1, s1p0, s1p1][fpair]
        #pragma unroll
        for (int k4 = 0; k4 < 16; k4++) {
            float4 x0 = ai0[k4], y00 = aj00[k4], y01 = aj01[k4];
            float4 x1 = ai1[k4], y10 = aj10[k4], y11 = aj11[k4];
            float T[4][4];
            T[0][0] = tanh_fast(x0.x - y00.x); T[0][1] = tanh_fast(x0.y - y00.y);
            T[0][2] = tanh_fast(x0.z - y00.z); T[0][3] = tanh_fast(x0.w - y00.w);
            T[1][0] = tanh_fast(x0.x - y01.x); T[1][1] = tanh_fast(x0.y - y01.y);
            T[1][2] = tanh_fast(x0.z - y01.z); T[1][3] = tanh_fast(x0.w - y01.w);
            T[2][0] = tanh_fast(x1.x - y10.x); T[2][1] = tanh_fast(x1.y - y10.y);
            T[2][2] = tanh_fast(x1.z - y10.z); T[2][3] = tanh_fast(x1.w - y10.w);
            T[3][0] = tanh_fast(x1.x - y11.x); T[3][1] = tanh_fast(x1.y - y11.y);
            T[3][2] = tanh_fast(x1.z - y11.z); T[3][3] = tanh_fast(x1.w - y11.w);
            #pragma unroll
            for (int v = 0; v < 4; v++) {
                const ulonglong2* wp = (const ulonglong2*)&sI2[(k4 * 4 + v) * 8];
                ulonglong2 wa = wp[0], wb = wp[1];   // one bcast, 4 pairs (2 samples)
                #pragma unroll
                for (int pi = 0; pi < 4; pi++) {
                    u64 tt = pack2(T[pi][v], T[pi][v]);
                    P[pi][0] = ffma2(tt, wa.x, P[pi][0]);
                    P[pi][1] = ffma2(tt, wa.y, P[pi][1]);
                    P[pi][2] = ffma2(tt, wb.x, P[pi][2]);
                    P[pi][3] = ffma2(tt, wb.y, P[pi][3]);
                }
            }
        }

        const int rb = i * 31 - ((i * (i - 1)) >> 1);
        #pragma unroll
        for (int pp = 0; pp < 2; pp++) {
            if (pp == 1 && !has2) break;
            int j = pp ? j1 : j0;
            int idx_ij = i * 31 + (j - 1);
            int idx_ji = j * 31 + i;
            float4 gi0 = __ldg((const float4*)(I3 + idx_ij * 8));
            float4 gi1 = __ldg((const float4*)(I3 + idx_ij * 8) + 1);
            float4 gj0 = __ldg((const float4*)(I3 + idx_ji * 8));
            float4 gj1 = __ldg((const float4*)(I3 + idx_ji * 8) + 1);
            int p = rb + (j - i - 1);
            #pragma unroll
            for (int s2 = 0; s2 < 2; s2++) {         // I3 loaded once, used by both samples
                int pi = s2 * 2 + pp;
                float t[8];
                unpack2(P[pi][0], t[0], t[1]); unpack2(P[pi][1], t[2], t[3]);
                unpack2(P[pi][2], t[4], t[5]); unpack2(P[pi][3], t[6], t[7]);
                #pragma unroll
                for (int f = 0; f < 8; f++) t[f] = tanh_exact(t[f]);
                float4 res;
                res.x = t[0]*gi0.x + t[1]*gi0.y + t[2]*gi0.z + t[3]*gi0.w;
                res.y = t[4]*gi1.x + t[5]*gi1.y + t[6]*gi1.z + t[7]*gi1.w;
                res.z = -(t[0]*gj0.x + t[1]*gj0.y + t[2]*gj0.z + t[3]*gj0.w);
                res.w = -(t[4]*gj1.x + t[5]*gj1.y + t[6]*gj1.z + t[7]*gj1.w);
                ((float4*)(sPair + s2 * NPAIR * 4))[p] = res;   // bufT2 region (dead)
            }
        }
    }
    __syncthreads();

    // ---- deterministic reduction + output (64 threads = 2 samples x 32 obj) ----
    if (tid < 64) {
        const int s2 = tid >> 5, o = tid & 31;
        float a0 = sRes[tid * 2 + 0], a1 = sRes[tid * 2 + 1];
        const float2* sp2 = (const float2*)(sPair + s2 * NPAIR * 4);
        int rb = o * 31 - ((o * (o - 1)) >> 1);
        for (int j = o + 1; j < N_OBJ; j++) {
            float2 v = sp2[(rb + j - o - 1) * 2 + 0];
            a0 += v.x; a1 += v.y;
        }
        for (int k = 0; k < o; k++) {
            int p = k * 31 - ((k * (k - 1)) >> 1) + (o - k - 1);
            float2 v = sp2[p * 2 + 1];
            a0 += v.x; a1 += v.y;
        }
        float2 r; r.x = a0; r.y = a1;
        ((float2*)out)[(bid * 2 + s2) * N_OBJ + o] = r;
    }
}

extern "C" void kernel_launch(void* const* d_in, const int* in_sizes, int n_in,
                              void* d_out, int out_size) {
    const float* inputs = (const float*)d_in[0];
    const float* L1W    = (const float*)d_in[1];
    const float* L1b    = (const float*)d_in[2];
    const float* L2W    = (const float*)d_in[3];
    const float* L2b    = (const float*)d_in[4];
    const float* I1W    = (const float*)d_in[5];
    const float* I2W    = (const float*)d_in[6];
    const float* I3     = (const float*)d_in[7];
    const float* S1W    = (const float*)d_in[8];
    const float* S1b    = (const float*)d_in[9];
    const float* S2W    = (const float*)d_in[10];
    const float* S2b    = (const float*)d_in[11];
    float* out = (float*)d_out;

    magnet_main<<<S_TOT / 2, 256>>>(inputs, L1W, L1b, L2W, L2b,
                                    I1W, I2W, I3, S1W, S1b, S2W, S2b, out);
}